// round 13
// baseline (speedup 1.0000x reference)
#include <cuda_runtime.h>
#include <cuda_fp16.h>
#include <cstdint>

#define NN 100000
#define IND 256
#define HD 128
#define PAD 128          // max in-degree capacity per node (Poisson(16) -> max ~45)

// Scratch (static device globals — allocation-free per harness rules)
// NOTE: reference these ONLY from device code (host-side use yields the host
// shadow address, silently readable as zeros via ATS on GB300 — R10 bug).
__device__ int    g_cnt[NN];                    // in-degree (excl self loop)
__device__ int    g_csr[(size_t)NN * PAD];      // src lists bucketed by dst
__device__ __half g_xws[(size_t)NN * HD];       // (A@W)*dinv, fp16 (gather source)
__device__ __half g_h1[(size_t)NN * HD];        // relu output of conv1 (fp16)
__device__ float  g_bp1[IND * HD];              // tf32 + frag-permuted W1
__device__ float  g_bp2[HD * HD];               // tf32 + frag-permuted W2

// ---------------------------------------------------------------------------
__device__ __forceinline__ uint32_t f2tf32(float f) {
    uint32_t r;
    asm("cvt.rna.tf32.f32 %0, %1;" : "=r"(r) : "f"(f));
    return r;
}

// Setup: zero cnt + pre-round & frag-permute both weight matrices.
// Bp[k*128 + w*64 + lr*8 + nt] = tf32( W[k*128 + w*64 + nt*8 + lr] )
__global__ void setup_kernel(const float* __restrict__ W1,
                             const float* __restrict__ W2) {
    int i = blockIdx.x * blockDim.x + threadIdx.x;
    if (i < NN) g_cnt[i] = 0;
    if (i < IND * HD) {
        int k  = i >> 7;
        int r  = i & 127;
        int w  = r >> 6;
        int lr = (r >> 3) & 7;
        int nt = r & 7;
        int srcc = w * 64 + nt * 8 + lr;
        g_bp1[i] = __uint_as_float(f2tf32(W1[k * HD + srcc]));
        if (i < HD * HD)
            g_bp2[i] = __uint_as_float(f2tf32(W2[k * HD + srcc]));
    }
}

__global__ void csr_fill_kernel(const int* __restrict__ src,
                                const int* __restrict__ dst, int E) {
    int i = blockIdx.x * blockDim.x + threadIdx.x;
    if (i >= E) return;
    int d = dst[i];
    int pos = atomicAdd(&g_cnt[d], 1);
    if (pos < PAD) g_csr[(size_t)d * PAD + pos] = src[i];
}

__device__ __forceinline__ void cp16(uint32_t saddr, const void* g, int sz) {
    asm volatile("cp.async.ca.shared.global [%0], [%1], 16, %2;"
                 :: "r"(saddr), "l"(g), "r"(sz));
}

// ---------------------------------------------------------------------------
// tf32 tensor-core GEMM, 2-stage cp.async pipeline, frag-permuted B.
// C = A[M x K] @ B[K x 128]; epilogue scales row by rsqrt(1+cnt), fp16 g_xws.
// CTA 128x128, BK=32, 8 warps (4m x 2n), warp tile 32x64.
// USE_H1=false: A = x (float, kernel arg), B = g_bp1.
// USE_H1=true : A = g_h1 (half, device symbol), B = g_bp2.
// ---------------------------------------------------------------------------
template<int K, bool USE_H1>
__global__ void __launch_bounds__(256) mma_gemm_kernel(const float* __restrict__ Axf,
                                                       int M)
{
    constexpr bool AHALF = USE_H1;
    constexpr int BM = 128, BK = 32;
    constexpr int ASTR = AHALF ? (BK + 8) : (BK + 4);   // halves:40 / floats:36
    constexpr int ASZ_B = BM * ASTR * (AHALF ? 2 : 4);  // A stage bytes
    constexpr int BSZ_B = BK * HD * 4;                  // 16384 (permuted, no pad)
    constexpr int STG_B = ASZ_B + BSZ_B;
    constexpr int TILES = K / BK;
    extern __shared__ char smem[];

    const float*  Bp = USE_H1 ? g_bp2 : g_bp1;          // device-side symbol ref
    const __half* Ah = g_h1;                            // device-side symbol ref

    const int tid  = threadIdx.x;
    const int wid  = tid >> 5;
    const int lane = tid & 31;
    const int row0 = blockIdx.x * BM;
    const int wm   = (wid & 3) * 32;
    const int wn   = (wid >> 2) * 64;
    const int lr   = lane >> 2;
    const int lc   = lane & 3;

    uint32_t sbase = (uint32_t)(uint64_t)__cvta_generic_to_shared(smem);

    float acc[2][8][4];
    #pragma unroll
    for (int mt = 0; mt < 2; mt++)
        #pragma unroll
        for (int nt = 0; nt < 8; nt++)
            #pragma unroll
            for (int i = 0; i < 4; i++) acc[mt][nt][i] = 0.0f;

    auto load_tile = [&](int t, int stage) {
        uint32_t as = sbase + (uint32_t)(stage * STG_B);
        uint32_t bs = as + (uint32_t)ASZ_B;
        if (AHALF) {
            #pragma unroll
            for (int i = 0; i < 2; i++) {
                int idx = tid + i * 256;          // 0..511
                int r   = idx >> 2;               // 0..127
                int k8  = (idx & 3) << 3;         // 0,8,16,24
                int gr  = row0 + r;
                int sz  = (gr < M) ? 16 : 0;
                int grc = (gr < M) ? gr : (M - 1);
                cp16(as + (uint32_t)(r * ASTR + k8) * 2u,
                     Ah + (size_t)grc * K + t * BK + k8, sz);
            }
        } else {
            #pragma unroll
            for (int i = 0; i < 4; i++) {
                int idx = tid + i * 256;
                int r   = idx >> 3;
                int k4  = (idx & 7) << 2;
                int gr  = row0 + r;
                int sz  = (gr < M) ? 16 : 0;
                int grc = (gr < M) ? gr : (M - 1);
                cp16(as + (uint32_t)(r * ASTR + k4) * 4u,
                     Axf + (size_t)grc * K + t * BK + k4, sz);
            }
        }
        // B: straight linear copy (permuted layout identical in gmem & smem)
        #pragma unroll
        for (int i = 0; i < 4; i++) {
            int idx = tid + i * 256;              // 0..1023 chunks of 16B
            cp16(bs + (uint32_t)idx * 16u,
                 Bp + (size_t)t * BK * HD + idx * 4, 16);
        }
    };

    load_tile(0, 0);
    asm volatile("cp.async.commit_group;");

    for (int t = 0; t < TILES; t++) {
        if (t + 1 < TILES) {
            load_tile(t + 1, (t + 1) & 1);
            asm volatile("cp.async.commit_group;");
            asm volatile("cp.async.wait_group 1;");
        } else {
            asm volatile("cp.async.wait_group 0;");
        }
        __syncthreads();

        const char* stg = smem + (t & 1) * STG_B;

        #pragma unroll
        for (int ks = 0; ks < 4; ks++) {
            int kb = ks * 8;
            uint32_t a[2][4];
            #pragma unroll
            for (int mt = 0; mt < 2; mt++) {
                int m = wm + mt * 16;
                if (AHALF) {
                    const __half* As = (const __half*)stg;
                    a[mt][0] = f2tf32(__half2float(As[(m + lr)     * ASTR + kb + lc]));
                    a[mt][1] = f2tf32(__half2float(As[(m + lr + 8) * ASTR + kb + lc]));
                    a[mt][2] = f2tf32(__half2float(As[(m + lr)     * ASTR + kb + lc + 4]));
                    a[mt][3] = f2tf32(__half2float(As[(m + lr + 8) * ASTR + kb + lc + 4]));
                } else {
                    const float* As = (const float*)stg;
                    a[mt][0] = f2tf32(As[(m + lr)     * ASTR + kb + lc]);
                    a[mt][1] = f2tf32(As[(m + lr + 8) * ASTR + kb + lc]);
                    a[mt][2] = f2tf32(As[(m + lr)     * ASTR + kb + lc + 4]);
                    a[mt][3] = f2tf32(As[(m + lr + 8) * ASTR + kb + lc + 4]);
                }
            }
            // B frags: vectorized from permuted layout.
            // b[nt][0] = Bs[(kb+lc)*128 + wn + lr*8 + nt], b[nt][1] row kb+lc+4
            const float* Bs = (const float*)(stg + ASZ_B);
            int rb0 = (kb + lc) * HD + wn + lr * 8;
            int rb1 = rb0 + 4 * HD;
            float4 b0a = *(const float4*)&Bs[rb0];
            float4 b0b = *(const float4*)&Bs[rb0 + 4];
            float4 b1a = *(const float4*)&Bs[rb1];
            float4 b1b = *(const float4*)&Bs[rb1 + 4];
            const float b0[8] = {b0a.x, b0a.y, b0a.z, b0a.w, b0b.x, b0b.y, b0b.z, b0b.w};
            const float b1[8] = {b1a.x, b1a.y, b1a.z, b1a.w, b1b.x, b1b.y, b1b.z, b1b.w};

            #pragma unroll
            for (int mt = 0; mt < 2; mt++)
                #pragma unroll
                for (int nt = 0; nt < 8; nt++) {
                    asm volatile(
                        "mma.sync.aligned.m16n8k8.row.col.f32.tf32.tf32.f32 "
                        "{%0,%1,%2,%3}, {%4,%5,%6,%7}, {%8,%9}, {%0,%1,%2,%3};"
                        : "+f"(acc[mt][nt][0]), "+f"(acc[mt][nt][1]),
                          "+f"(acc[mt][nt][2]), "+f"(acc[mt][nt][3])
                        : "r"(a[mt][0]), "r"(a[mt][1]), "r"(a[mt][2]), "r"(a[mt][3]),
                          "r"(__float_as_uint(b0[nt])), "r"(__float_as_uint(b1[nt])));
                }
        }
        __syncthreads();
    }

    // ---- epilogue: scale by rsqrt(1+cnt), write fp16 g_xws ----
    #pragma unroll
    for (int mt = 0; mt < 2; mt++) {
        int r1 = row0 + wm + mt * 16 + lr;
        int r2 = r1 + 8;
        float s1 = (r1 < M) ? rsqrtf(1.0f + (float)g_cnt[r1]) : 0.f;
        float s2 = (r2 < M) ? rsqrtf(1.0f + (float)g_cnt[r2]) : 0.f;
        #pragma unroll
        for (int nt = 0; nt < 8; nt++) {
            int c = wn + nt * 8 + lc * 2;
            if (r1 < M)
                *(__half2*)(g_xws + (size_t)r1 * HD + c) =
                    __floats2half2_rn(acc[mt][nt][0] * s1, acc[mt][nt][1] * s1);
            if (r2 < M)
                *(__half2*)(g_xws + (size_t)r2 * HD + c) =
                    __floats2half2_rn(acc[mt][nt][2] * s2, acc[mt][nt][3] * s2);
        }
    }
}

// ---------------------------------------------------------------------------
// fp16 gather helper: lane owns features [4L, 4L+4) = 8 bytes
// ---------------------------------------------------------------------------
__device__ __forceinline__ void add_row(float4& sum, const __half* base, int s, int lane) {
    uint2 raw = *(const uint2*)(base + (size_t)s * HD + lane * 4);
    float2 p0 = __half22float2(*(const __half2*)&raw.x);
    float2 p1 = __half22float2(*(const __half2*)&raw.y);
    sum.x += p0.x;  sum.y += p0.y;  sum.z += p1.x;  sum.w += p1.y;
}

// ---------------------------------------------------------------------------
// agg1: warp per node. sum = xws[n] + sum_e xws[csr[n][e]]
//       h1 = relu(rsqrt(1+cnt)*sum + b1) -> fp16
// ---------------------------------------------------------------------------
__global__ void __launch_bounds__(256) agg1_kernel(const float* __restrict__ b1) {
    int n = (int)((blockIdx.x * 256u + threadIdx.x) >> 5);
    if (n >= NN) return;
    int lane = threadIdx.x & 31;
    int cnt = g_cnt[n];
    const int* lst = g_csr + (size_t)n * PAD;

    float4 sum = make_float4(0.f, 0.f, 0.f, 0.f);
    add_row(sum, g_xws, n, lane);               // self loop

    int e = 0;
    for (; e + 4 <= cnt; e += 4) {
        int s0 = __ldg(&lst[e]);
        int s1 = __ldg(&lst[e + 1]);
        int s2 = __ldg(&lst[e + 2]);
        int s3 = __ldg(&lst[e + 3]);
        add_row(sum, g_xws, s0, lane);
        add_row(sum, g_xws, s1, lane);
        add_row(sum, g_xws, s2, lane);
        add_row(sum, g_xws, s3, lane);
    }
    for (; e < cnt; e++) add_row(sum, g_xws, __ldg(&lst[e]), lane);

    float s = rsqrtf(1.0f + (float)cnt);
    float4 b = ((const float4*)b1)[lane];
    float hx = fmaxf(fmaf(sum.x, s, b.x), 0.f);
    float hy = fmaxf(fmaf(sum.y, s, b.y), 0.f);
    float hz = fmaxf(fmaf(sum.z, s, b.z), 0.f);
    float hw = fmaxf(fmaf(sum.w, s, b.w), 0.f);
    uint2 o;
    *(__half2*)&o.x = __floats2half2_rn(hx, hy);
    *(__half2*)&o.y = __floats2half2_rn(hz, hw);
    *(uint2*)(g_h1 + (size_t)n * HD + lane * 4) = o;
}

// ---------------------------------------------------------------------------
// agg2 + output: warp per node.
// ---------------------------------------------------------------------------
__global__ void __launch_bounds__(256) agg2out_kernel(const float* __restrict__ hnode,
                                                      const float* __restrict__ b2,
                                                      const float* __restrict__ Wc,
                                                      const float* __restrict__ bc,
                                                      const float* __restrict__ Wf,
                                                      const float* __restrict__ bf,
                                                      float* __restrict__ out)
{
    int n = (int)((blockIdx.x * 256u + threadIdx.x) >> 5);
    if (n >= NN) return;
    int lane = threadIdx.x & 31;
    int cnt = g_cnt[n];
    const int* lst = g_csr + (size_t)n * PAD;

    float4 sum = make_float4(0.f, 0.f, 0.f, 0.f);
    add_row(sum, g_xws, n, lane);               // self loop

    int e = 0;
    for (; e + 4 <= cnt; e += 4) {
        int s0 = __ldg(&lst[e]);
        int s1 = __ldg(&lst[e + 1]);
        int s2 = __ldg(&lst[e + 2]);
        int s3 = __ldg(&lst[e + 3]);
        add_row(sum, g_xws, s0, lane);
        add_row(sum, g_xws, s1, lane);
        add_row(sum, g_xws, s2, lane);
        add_row(sum, g_xws, s3, lane);
    }
    for (; e < cnt; e++) add_row(sum, g_xws, __ldg(&lst[e]), lane);

    float s     = rsqrtf(1.0f + (float)cnt);
    float alpha = hnode[n];
    float beta  = 1.0f - alpha;
    float4 bv   = ((const float4*)b2)[lane];

    // h1 (fp16 -> fp32)
    float4 h1v;
    {
        uint2 raw = *(const uint2*)(g_h1 + (size_t)n * HD + lane * 4);
        float2 p0 = __half22float2(*(const __half2*)&raw.x);
        float2 p1 = __half22float2(*(const __half2*)&raw.y);
        h1v = make_float4(p0.x, p0.y, p1.x, p1.y);
    }

    float4 h2, ha;
    h2.x = fmaxf(fmaf(sum.x, s, bv.x), 0.f);
    h2.y = fmaxf(fmaf(sum.y, s, bv.y), 0.f);
    h2.z = fmaxf(fmaf(sum.z, s, bv.z), 0.f);
    h2.w = fmaxf(fmaf(sum.w, s, bv.w), 0.f);
    ha.x = alpha * h2.x + beta * h1v.x;
    ha.y = alpha * h2.y + beta * h1v.y;
    ha.z = alpha * h2.z + beta * h1v.z;
    ha.w = alpha * h2.w + beta * h1v.w;

    float4 wc0 = *(const float4*)(Wc + lane * 8);
    float4 wc1 = *(const float4*)(Wc + lane * 8 + 4);
    float4 wf0 = *(const float4*)(Wf + lane * 8);
    float4 wf1 = *(const float4*)(Wf + lane * 8 + 4);

    float c0 = h1v.x * wc0.x + h1v.y * wc0.z + h1v.z * wc1.x + h1v.w * wc1.z;
    float c1 = h1v.x * wc0.y + h1v.y * wc0.w + h1v.z * wc1.y + h1v.w * wc1.w;
    float f0 = ha.x * wf0.x + ha.y * wf0.z + ha.z * wf1.x + ha.w * wf1.z;
    float f1 = ha.x * wf0.y + ha.y * wf0.w + ha.z * wf1.y + ha.w * wf1.w;

    #pragma unroll
    for (int off = 16; off > 0; off >>= 1) {
        c0 += __shfl_xor_sync(0xFFFFFFFFu, c0, off);
        c1 += __shfl_xor_sync(0xFFFFFFFFu, c1, off);
        f0 += __shfl_xor_sync(0xFFFFFFFFu, f0, off);
        f1 += __shfl_xor_sync(0xFFFFFFFFu, f1, off);
    }
    if (lane == 0) {
        out[2 * (size_t)n + 0] = 0.5f * (c0 + bc[0]) + 0.5f * (f0 + bf[0]);
        out[2 * (size_t)n + 1] = 0.5f * (c1 + bc[1]) + 0.5f * (f1 + bf[1]);
    }
}

// ---------------------------------------------------------------------------
extern "C" void kernel_launch(void* const* d_in, const int* in_sizes, int n_in,
                              void* d_out, int out_size)
{
    const float* x     = (const float*)d_in[0];
    const int*   ei    = (const int*)d_in[1];     // int32 (jax x64 disabled)
    const float* hnode = (const float*)d_in[2];
    const float* W1    = (const float*)d_in[3];
    const float* b1    = (const float*)d_in[4];
    const float* W2    = (const float*)d_in[5];
    const float* b2    = (const float*)d_in[6];
    const float* Wc    = (const float*)d_in[7];
    const float* bc    = (const float*)d_in[8];
    const float* Wf    = (const float*)d_in[9];
    const float* bf    = (const float*)d_in[10];
    float* out = (float*)d_out;

    int E = in_sizes[1] / 2;
    const int* src = ei;
    const int* dst = ei + E;

    // 2-stage dynamic smem: gemm1 (18432+16384)*2 = 69632B, gemm2 (10240+16384)*2 = 53248B
    constexpr int SMEM1 = 2 * (128 * 36 * 4 + 32 * HD * 4);
    constexpr int SMEM2 = 2 * (128 * 40 * 2 + 32 * HD * 4);
    cudaFuncSetAttribute(mma_gemm_kernel<IND, false>,
                         cudaFuncAttributeMaxDynamicSharedMemorySize, SMEM1);
    cudaFuncSetAttribute(mma_gemm_kernel<HD, true>,
                         cudaFuncAttributeMaxDynamicSharedMemorySize, SMEM2);

    // Setup (zero cnt + weight pre-round/permute) + CSR build
    setup_kernel<<<(NN + 255) / 256, 256>>>(W1, W2);
    csr_fill_kernel<<<(E + 255) / 256, 256>>>(src, dst, E);

    // Conv1
    mma_gemm_kernel<IND, false><<<(NN + 127) / 128, 256, SMEM1>>>(x, NN);
    agg1_kernel<<<((size_t)NN * 32 + 255) / 256, 256>>>(b1);

    // Conv2 + fused blend/heads/output
    mma_gemm_kernel<HD, true><<<(NN + 127) / 128, 256, SMEM2>>>(nullptr, NN);
    agg2out_kernel<<<((size_t)NN * 32 + 255) / 256, 256>>>(hnode, b2, Wc, bc, Wf, bf, out);
}

// round 14
// speedup vs baseline: 1.1845x; 1.1845x over previous
#include <cuda_runtime.h>
#include <cuda_fp16.h>
#include <cstdint>

#define NN 100000
#define IND 256
#define HD 128
#define PAD 128          // max in-degree capacity per node (Poisson(16) -> max ~45)

// Scratch (static device globals — allocation-free per harness rules)
// NOTE: reference these ONLY from device code (host-side use yields the host
// shadow address, silently readable as zeros via ATS on GB300 — R10 bug).
__device__ int    g_cnt[NN];                    // in-degree (excl self loop)
__device__ int    g_csr[(size_t)NN * PAD];      // src lists bucketed by dst
__device__ __half g_xws[(size_t)NN * HD];       // (A@W)*dinv, fp16 (gather source)
__device__ __half g_h1[(size_t)NN * HD];        // relu output of conv1 (fp16)
__device__ float  g_bp1[IND * HD];              // tf32 + frag-blocked W1
__device__ float  g_bp2[HD * HD];               // tf32 + frag-blocked W2

// ---------------------------------------------------------------------------
__device__ __forceinline__ uint32_t f2tf32(float f) {
    uint32_t r;
    asm("cvt.rna.tf32.f32 %0, %1;" : "=r"(r) : "f"(f));
    return r;
}

// Setup: zero cnt + pre-round & frag-block both weight matrices.
// Per BK=32 tile t: 16 blocks of 256 floats, block = (ks*2+j)*2 + w.
// Within block: [half4][lane][f]; stored element =
//   W[t*32 + ks*8 + j*4 + lc][w*64 + (half4*4+f)*8 + lr],  lane = lr*4+lc.
// Thread frag load is then lane-stride-16B => conflict-free LDS.128.
__global__ void setup_kernel(const float* __restrict__ W1,
                             const float* __restrict__ W2) {
    int i = blockIdx.x * blockDim.x + threadIdx.x;
    if (i < NN) g_cnt[i] = 0;
    if (i < IND * HD) {
        int t     = i >> 12;            // BK-tile (4096 floats each)
        int d     = i & 4095;
        int block = d >> 8;             // 0..15
        int ks    = block >> 2;         // 0..3
        int j     = (block >> 1) & 1;   // 0..1 (b0 / b1 rows)
        int w     = block & 1;          // warp n-half
        int q     = d & 255;
        int half4 = q >> 7;             // 0..1
        int lane  = (q >> 2) & 31;
        int f     = q & 3;
        int lr = lane >> 2, lc = lane & 3;
        int k = t * 32 + ks * 8 + j * 4 + lc;
        int n = w * 64 + (half4 * 4 + f) * 8 + lr;
        g_bp1[i] = __uint_as_float(f2tf32(W1[k * HD + n]));
        if (i < HD * HD)
            g_bp2[i] = __uint_as_float(f2tf32(W2[k * HD + n]));
    }
}

__global__ void csr_fill_kernel(const int* __restrict__ src,
                                const int* __restrict__ dst, int E) {
    int i = blockIdx.x * blockDim.x + threadIdx.x;
    if (i >= E) return;
    int d = dst[i];
    int pos = atomicAdd(&g_cnt[d], 1);
    if (pos < PAD) g_csr[(size_t)d * PAD + pos] = src[i];
}

__device__ __forceinline__ void cp16(uint32_t saddr, const void* g, int sz) {
    asm volatile("cp.async.ca.shared.global [%0], [%1], 16, %2;"
                 :: "r"(saddr), "l"(g), "r"(sz));
}

// ---------------------------------------------------------------------------
// tf32 tensor-core GEMM, 2-stage cp.async pipeline, frag-blocked B.
// C = A[M x K] @ B[K x 128]; epilogue scales row by rsqrt(1+cnt), fp16 g_xws.
// CTA 128x128, BK=32, 8 warps (4m x 2n), warp tile 32x64.
// USE_H1=false: A = x (float, kernel arg), B = g_bp1.
// USE_H1=true : A = g_h1 (half, device symbol), B = g_bp2.
// ---------------------------------------------------------------------------
template<int K, bool USE_H1>
__global__ void __launch_bounds__(256) mma_gemm_kernel(const float* __restrict__ Axf,
                                                       int M)
{
    constexpr bool AHALF = USE_H1;
    constexpr int BM = 128, BK = 32;
    constexpr int ASTR = AHALF ? (BK + 8) : (BK + 4);   // halves:40 / floats:36
    constexpr int ASZ_B = BM * ASTR * (AHALF ? 2 : 4);  // A stage bytes
    constexpr int BSZ_B = BK * HD * 4;                  // 16384 (frag-blocked)
    constexpr int STG_B = ASZ_B + BSZ_B;
    constexpr int TILES = K / BK;
    extern __shared__ char smem[];

    const float*  Bp = USE_H1 ? g_bp2 : g_bp1;          // device-side symbol ref
    const __half* Ah = g_h1;                            // device-side symbol ref

    const int tid  = threadIdx.x;
    const int wid  = tid >> 5;
    const int lane = tid & 31;
    const int row0 = blockIdx.x * BM;
    const int wm   = (wid & 3) * 32;
    const int wnh  = (wid >> 2);         // warp n-half: 0 or 1
    const int wn   = wnh * 64;
    const int lr   = lane >> 2;
    const int lc   = lane & 3;

    uint32_t sbase = (uint32_t)(uint64_t)__cvta_generic_to_shared(smem);

    float acc[2][8][4];
    #pragma unroll
    for (int mt = 0; mt < 2; mt++)
        #pragma unroll
        for (int nt = 0; nt < 8; nt++)
            #pragma unroll
            for (int i = 0; i < 4; i++) acc[mt][nt][i] = 0.0f;

    auto load_tile = [&](int t, int stage) {
        uint32_t as = sbase + (uint32_t)(stage * STG_B);
        uint32_t bs = as + (uint32_t)ASZ_B;
        if (AHALF) {
            #pragma unroll
            for (int i = 0; i < 2; i++) {
                int idx = tid + i * 256;          // 0..511
                int r   = idx >> 2;               // 0..127
                int k8  = (idx & 3) << 3;         // 0,8,16,24
                int gr  = row0 + r;
                int sz  = (gr < M) ? 16 : 0;
                int grc = (gr < M) ? gr : (M - 1);
                cp16(as + (uint32_t)(r * ASTR + k8) * 2u,
                     Ah + (size_t)grc * K + t * BK + k8, sz);
            }
        } else {
            #pragma unroll
            for (int i = 0; i < 4; i++) {
                int idx = tid + i * 256;
                int r   = idx >> 3;
                int k4  = (idx & 7) << 2;
                int gr  = row0 + r;
                int sz  = (gr < M) ? 16 : 0;
                int grc = (gr < M) ? gr : (M - 1);
                cp16(as + (uint32_t)(r * ASTR + k4) * 4u,
                     Axf + (size_t)grc * K + t * BK + k4, sz);
            }
        }
        // B: straight linear copy (frag-blocked layout identical gmem & smem)
        #pragma unroll
        for (int i = 0; i < 4; i++) {
            int idx = tid + i * 256;              // 0..1023 chunks of 16B
            cp16(bs + (uint32_t)idx * 16u,
                 Bp + (size_t)t * BK * HD + idx * 4, 16);
        }
    };

    load_tile(0, 0);
    asm volatile("cp.async.commit_group;");

    for (int t = 0; t < TILES; t++) {
        if (t + 1 < TILES) {
            load_tile(t + 1, (t + 1) & 1);
            asm volatile("cp.async.commit_group;");
            asm volatile("cp.async.wait_group 1;");
        } else {
            asm volatile("cp.async.wait_group 0;");
        }
        __syncthreads();

        const char* stg = smem + (t & 1) * STG_B;

        #pragma unroll
        for (int ks = 0; ks < 4; ks++) {
            int kb = ks * 8;
            uint32_t a[2][4];
            #pragma unroll
            for (int mt = 0; mt < 2; mt++) {
                int m = wm + mt * 16;
                if (AHALF) {
                    const __half* As = (const __half*)stg;
                    a[mt][0] = f2tf32(__half2float(As[(m + lr)     * ASTR + kb + lc]));
                    a[mt][1] = f2tf32(__half2float(As[(m + lr + 8) * ASTR + kb + lc]));
                    a[mt][2] = f2tf32(__half2float(As[(m + lr)     * ASTR + kb + lc + 4]));
                    a[mt][3] = f2tf32(__half2float(As[(m + lr + 8) * ASTR + kb + lc + 4]));
                } else {
                    const float* As = (const float*)stg;
                    a[mt][0] = f2tf32(As[(m + lr)     * ASTR + kb + lc]);
                    a[mt][1] = f2tf32(As[(m + lr + 8) * ASTR + kb + lc]);
                    a[mt][2] = f2tf32(As[(m + lr)     * ASTR + kb + lc + 4]);
                    a[mt][3] = f2tf32(As[(m + lr + 8) * ASTR + kb + lc + 4]);
                }
            }
            // B frags: 4 conflict-free LDS.128 (lane-stride = 16B inside block)
            const float* Bs = (const float*)(stg + ASZ_B);
            int blk0 = ((ks * 2 + 0) * 2 + wnh) * 256;   // j=0 rows kb+lc
            int blk1 = blk0 + 512;                        // j=1 rows kb+4+lc
            float4 b0a = *(const float4*)&Bs[blk0 +       lane * 4];
            float4 b0b = *(const float4*)&Bs[blk0 + 128 + lane * 4];
            float4 b1a = *(const float4*)&Bs[blk1 +       lane * 4];
            float4 b1b = *(const float4*)&Bs[blk1 + 128 + lane * 4];
            const float b0[8] = {b0a.x, b0a.y, b0a.z, b0a.w, b0b.x, b0b.y, b0b.z, b0b.w};
            const float b1[8] = {b1a.x, b1a.y, b1a.z, b1a.w, b1b.x, b1b.y, b1b.z, b1b.w};

            #pragma unroll
            for (int mt = 0; mt < 2; mt++)
                #pragma unroll
                for (int nt = 0; nt < 8; nt++) {
                    asm volatile(
                        "mma.sync.aligned.m16n8k8.row.col.f32.tf32.tf32.f32 "
                        "{%0,%1,%2,%3}, {%4,%5,%6,%7}, {%8,%9}, {%0,%1,%2,%3};"
                        : "+f"(acc[mt][nt][0]), "+f"(acc[mt][nt][1]),
                          "+f"(acc[mt][nt][2]), "+f"(acc[mt][nt][3])
                        : "r"(a[mt][0]), "r"(a[mt][1]), "r"(a[mt][2]), "r"(a[mt][3]),
                          "r"(__float_as_uint(b0[nt])), "r"(__float_as_uint(b1[nt])));
                }
        }
        __syncthreads();
    }

    // ---- epilogue: scale by rsqrt(1+cnt), write fp16 g_xws ----
    #pragma unroll
    for (int mt = 0; mt < 2; mt++) {
        int r1 = row0 + wm + mt * 16 + lr;
        int r2 = r1 + 8;
        float s1 = (r1 < M) ? rsqrtf(1.0f + (float)g_cnt[r1]) : 0.f;
        float s2 = (r2 < M) ? rsqrtf(1.0f + (float)g_cnt[r2]) : 0.f;
        #pragma unroll
        for (int nt = 0; nt < 8; nt++) {
            int c = wn + nt * 8 + lc * 2;
            if (r1 < M)
                *(__half2*)(g_xws + (size_t)r1 * HD + c) =
                    __floats2half2_rn(acc[mt][nt][0] * s1, acc[mt][nt][1] * s1);
            if (r2 < M)
                *(__half2*)(g_xws + (size_t)r2 * HD + c) =
                    __floats2half2_rn(acc[mt][nt][2] * s2, acc[mt][nt][3] * s2);
        }
    }
}

// ---------------------------------------------------------------------------
// fp16 gather helper: lane owns features [4L, 4L+4) = 8 bytes
// ---------------------------------------------------------------------------
__device__ __forceinline__ void add_row(float4& sum, const __half* base, int s, int lane) {
    uint2 raw = *(const uint2*)(base + (size_t)s * HD + lane * 4);
    float2 p0 = __half22float2(*(const __half2*)&raw.x);
    float2 p1 = __half22float2(*(const __half2*)&raw.y);
    sum.x += p0.x;  sum.y += p0.y;  sum.z += p1.x;  sum.w += p1.y;
}

// ---------------------------------------------------------------------------
// agg1: warp per node. sum = xws[n] + sum_e xws[csr[n][e]]
//       h1 = relu(rsqrt(1+cnt)*sum + b1) -> fp16
// ---------------------------------------------------------------------------
__global__ void __launch_bounds__(256) agg1_kernel(const float* __restrict__ b1) {
    int n = (int)((blockIdx.x * 256u + threadIdx.x) >> 5);
    if (n >= NN) return;
    int lane = threadIdx.x & 31;
    int cnt = g_cnt[n];
    const int* lst = g_csr + (size_t)n * PAD;

    float4 sum = make_float4(0.f, 0.f, 0.f, 0.f);
    add_row(sum, g_xws, n, lane);               // self loop

    int e = 0;
    for (; e + 4 <= cnt; e += 4) {
        int s0 = __ldg(&lst[e]);
        int s1 = __ldg(&lst[e + 1]);
        int s2 = __ldg(&lst[e + 2]);
        int s3 = __ldg(&lst[e + 3]);
        add_row(sum, g_xws, s0, lane);
        add_row(sum, g_xws, s1, lane);
        add_row(sum, g_xws, s2, lane);
        add_row(sum, g_xws, s3, lane);
    }
    for (; e < cnt; e++) add_row(sum, g_xws, __ldg(&lst[e]), lane);

    float s = rsqrtf(1.0f + (float)cnt);
    float4 b = ((const float4*)b1)[lane];
    float hx = fmaxf(fmaf(sum.x, s, b.x), 0.f);
    float hy = fmaxf(fmaf(sum.y, s, b.y), 0.f);
    float hz = fmaxf(fmaf(sum.z, s, b.z), 0.f);
    float hw = fmaxf(fmaf(sum.w, s, b.w), 0.f);
    uint2 o;
    *(__half2*)&o.x = __floats2half2_rn(hx, hy);
    *(__half2*)&o.y = __floats2half2_rn(hz, hw);
    *(uint2*)(g_h1 + (size_t)n * HD + lane * 4) = o;
}

// ---------------------------------------------------------------------------
// agg2 + output: warp per node.
// ---------------------------------------------------------------------------
__global__ void __launch_bounds__(256) agg2out_kernel(const float* __restrict__ hnode,
                                                      const float* __restrict__ b2,
                                                      const float* __restrict__ Wc,
                                                      const float* __restrict__ bc,
                                                      const float* __restrict__ Wf,
                                                      const float* __restrict__ bf,
                                                      float* __restrict__ out)
{
    int n = (int)((blockIdx.x * 256u + threadIdx.x) >> 5);
    if (n >= NN) return;
    int lane = threadIdx.x & 31;
    int cnt = g_cnt[n];
    const int* lst = g_csr + (size_t)n * PAD;

    float4 sum = make_float4(0.f, 0.f, 0.f, 0.f);
    add_row(sum, g_xws, n, lane);               // self loop

    int e = 0;
    for (; e + 4 <= cnt; e += 4) {
        int s0 = __ldg(&lst[e]);
        int s1 = __ldg(&lst[e + 1]);
        int s2 = __ldg(&lst[e + 2]);
        int s3 = __ldg(&lst[e + 3]);
        add_row(sum, g_xws, s0, lane);
        add_row(sum, g_xws, s1, lane);
        add_row(sum, g_xws, s2, lane);
        add_row(sum, g_xws, s3, lane);
    }
    for (; e < cnt; e++) add_row(sum, g_xws, __ldg(&lst[e]), lane);

    float s     = rsqrtf(1.0f + (float)cnt);
    float alpha = hnode[n];
    float beta  = 1.0f - alpha;
    float4 bv   = ((const float4*)b2)[lane];

    // h1 (fp16 -> fp32)
    float4 h1v;
    {
        uint2 raw = *(const uint2*)(g_h1 + (size_t)n * HD + lane * 4);
        float2 p0 = __half22float2(*(const __half2*)&raw.x);
        float2 p1 = __half22float2(*(const __half2*)&raw.y);
        h1v = make_float4(p0.x, p0.y, p1.x, p1.y);
    }

    float4 h2, ha;
    h2.x = fmaxf(fmaf(sum.x, s, bv.x), 0.f);
    h2.y = fmaxf(fmaf(sum.y, s, bv.y), 0.f);
    h2.z = fmaxf(fmaf(sum.z, s, bv.z), 0.f);
    h2.w = fmaxf(fmaf(sum.w, s, bv.w), 0.f);
    ha.x = alpha * h2.x + beta * h1v.x;
    ha.y = alpha * h2.y + beta * h1v.y;
    ha.z = alpha * h2.z + beta * h1v.z;
    ha.w = alpha * h2.w + beta * h1v.w;

    float4 wc0 = *(const float4*)(Wc + lane * 8);
    float4 wc1 = *(const float4*)(Wc + lane * 8 + 4);
    float4 wf0 = *(const float4*)(Wf + lane * 8);
    float4 wf1 = *(const float4*)(Wf + lane * 8 + 4);

    float c0 = h1v.x * wc0.x + h1v.y * wc0.z + h1v.z * wc1.x + h1v.w * wc1.z;
    float c1 = h1v.x * wc0.y + h1v.y * wc0.w + h1v.z * wc1.y + h1v.w * wc1.w;
    float f0 = ha.x * wf0.x + ha.y * wf0.z + ha.z * wf1.x + ha.w * wf1.z;
    float f1 = ha.x * wf0.y + ha.y * wf0.w + ha.z * wf1.y + ha.w * wf1.w;

    #pragma unroll
    for (int off = 16; off > 0; off >>= 1) {
        c0 += __shfl_xor_sync(0xFFFFFFFFu, c0, off);
        c1 += __shfl_xor_sync(0xFFFFFFFFu, c1, off);
        f0 += __shfl_xor_sync(0xFFFFFFFFu, f0, off);
        f1 += __shfl_xor_sync(0xFFFFFFFFu, f1, off);
    }
    if (lane == 0) {
        out[2 * (size_t)n + 0] = 0.5f * (c0 + bc[0]) + 0.5f * (f0 + bf[0]);
        out[2 * (size_t)n + 1] = 0.5f * (c1 + bc[1]) + 0.5f * (f1 + bf[1]);
    }
}

// ---------------------------------------------------------------------------
extern "C" void kernel_launch(void* const* d_in, const int* in_sizes, int n_in,
                              void* d_out, int out_size)
{
    const float* x     = (const float*)d_in[0];
    const int*   ei    = (const int*)d_in[1];     // int32 (jax x64 disabled)
    const float* hnode = (const float*)d_in[2];
    const float* W1    = (const float*)d_in[3];
    const float* b1    = (const float*)d_in[4];
    const float* W2    = (const float*)d_in[5];
    const float* b2    = (const float*)d_in[6];
    const float* Wc    = (const float*)d_in[7];
    const float* bc    = (const float*)d_in[8];
    const float* Wf    = (const float*)d_in[9];
    const float* bf    = (const float*)d_in[10];
    float* out = (float*)d_out;

    int E = in_sizes[1] / 2;
    const int* src = ei;
    const int* dst = ei + E;

    // 2-stage dynamic smem: gemm1 69632B, gemm2 53248B (2 CTAs/SM both)
    constexpr int SMEM1 = 2 * (128 * 36 * 4 + 32 * HD * 4);
    constexpr int SMEM2 = 2 * (128 * 40 * 2 + 32 * HD * 4);
    cudaFuncSetAttribute(mma_gemm_kernel<IND, false>,
                         cudaFuncAttributeMaxDynamicSharedMemorySize, SMEM1);
    cudaFuncSetAttribute(mma_gemm_kernel<HD, true>,
                         cudaFuncAttributeMaxDynamicSharedMemorySize, SMEM2);

    // Setup (zero cnt + weight pre-round/frag-block) + CSR build
    setup_kernel<<<(NN + 255) / 256, 256>>>(W1, W2);
    csr_fill_kernel<<<(E + 255) / 256, 256>>>(src, dst, E);

    // Conv1
    mma_gemm_kernel<IND, false><<<(NN + 127) / 128, 256, SMEM1>>>(x, NN);
    agg1_kernel<<<((size_t)NN * 32 + 255) / 256, 256>>>(b1);

    // Conv2 + fused blend/heads/output
    mma_gemm_kernel<HD, true><<<(NN + 127) / 128, 256, SMEM2>>>(nullptr, NN);
    agg2out_kernel<<<((size_t)NN * 32 + 255) / 256, 256>>>(hnode, b2, Wc, bc, Wf, bf, out);
}